// round 1
// baseline (speedup 1.0000x reference)
#include <cuda_runtime.h>
#include <stdint.h>

typedef unsigned long long ull;

#define NTOK   262144
#define NSLOT  524288     // NTOK * K
#define DIN    128
#define DOUT   128
#define NEXP   8
#define TILE_M 64

// Scratch (device globals per harness rules: no cudaMalloc anywhere).
__device__ float g_wt[NEXP * DIN * DOUT];            // transposed weights [e][i][o]
__device__ float g_ybuf[(size_t)NSLOT * DOUT];       // gate-scaled per-slot GEMM outputs

// ---------------------------------------------------------------------------
// Kernel A: transpose weight [e][o][i] -> g_wt [e][i][o]
// ---------------------------------------------------------------------------
__global__ void k_transpose(const float* __restrict__ W) {
    __shared__ float tile[32][33];
    const int e  = blockIdx.z;
    const int o0 = blockIdx.x * 32;
    const int i0 = blockIdx.y * 32;
    const float* Wb  = W    + (size_t)e * DOUT * DIN;
    float*       Wtb = g_wt + (size_t)e * DIN * DOUT;
    const int x = threadIdx.x, y = threadIdx.y;
    #pragma unroll
    for (int r = y; r < 32; r += 8)
        tile[r][x] = Wb[(o0 + r) * DIN + i0 + x];
    __syncthreads();
    #pragma unroll
    for (int r = y; r < 32; r += 8)
        Wtb[(i0 + r) * DOUT + o0 + x] = tile[x][r];
}

// ---------------------------------------------------------------------------
// Kernel B: grouped GEMM over expert-sorted slots.
// Tile: M=64 slots x N=128 outputs x K=128, fp32 with packed fma.rn.f32x2.
// Each thread: 4 rows x 8 cols (as 4 f32x2 col-pairs).
// Writes gate-scaled rows to g_ybuf[ss][*].
// ---------------------------------------------------------------------------
__global__ void __launch_bounds__(256, 2)
k_gemm(const float* __restrict__ inputs,
       const float* __restrict__ gates,     // flat [NSLOT]
       const int*   __restrict__ sei,       // sorted_expert_idxs
       const int*   __restrict__ ssi)       // sorted_scattered_idxs
{
    extern __shared__ float smem[];
    float* Xs = smem;                 // [64][128]
    float* Ws = smem + TILE_M * DIN;  // [128][128]  (g_wt layout: [i][o])

    __shared__ int   ss_sm[TILE_M];
    __shared__ float gate_sm[TILE_M];
    __shared__ int   exp_sm[TILE_M];
    __shared__ int   s_next;

    const int tx = threadIdx.x;
    const int s0 = blockIdx.x * TILE_M;

    if (tx < TILE_M) {
        const int ss = ssi[s0 + tx];
        ss_sm[tx]   = ss;
        gate_sm[tx] = gates[ss];
        exp_sm[tx]  = sei[s0 + tx];
    }
    __syncthreads();

    // Gather X tile: 64 rows x 128 floats (coalesced 512B per row).
    #pragma unroll
    for (int it = 0; it < 8; ++it) {
        const int idx = tx + 256 * it;           // 0..2047 float4 units
        const int m = idx >> 5, q = idx & 31;
        const float4 v = *(const float4*)(inputs + (size_t)(ss_sm[m] >> 1) * DIN + q * 4);
        *(float4*)(Xs + m * DIN + q * 4) = v;
    }

    const int rowbase = (tx >> 4) * 4;         // 0..60
    const int p       = (tx & 15) * 2;         // col-pair base 0..30

    int e_cur = exp_sm[0];
    while (true) {
        __syncthreads();  // Ws reuse / X-tile ready
        // Load W[e_cur] transposed tile (64 KB, L2-resident source).
        const float* __restrict__ Wsrc = g_wt + (size_t)e_cur * DIN * DOUT;
        #pragma unroll
        for (int it = 0; it < 16; ++it) {
            const int idx = (tx + 256 * it) * 4;
            *(float4*)(Ws + idx) = *(const float4*)(Wsrc + idx);
        }
        if (tx == 0) s_next = 1 << 30;
        __syncthreads();

        ull acc[4][4];
        #pragma unroll
        for (int r = 0; r < 4; ++r)
            #pragma unroll
            for (int c = 0; c < 4; ++c) acc[r][c] = 0ull;

        #pragma unroll 8
        for (int kk = 0; kk < DIN; kk += 4) {
            float4 xr[4];
            #pragma unroll
            for (int r = 0; r < 4; ++r)
                xr[r] = *(const float4*)(Xs + (rowbase + r) * DIN + kk);
            #pragma unroll
            for (int u = 0; u < 4; ++u) {
                const float* wrow = Ws + (kk + u) * DOUT + p;
                ull w[4];
                #pragma unroll
                for (int c = 0; c < 4; ++c)
                    w[c] = *(const ull*)(wrow + 32 * c);
                #pragma unroll
                for (int r = 0; r < 4; ++r) {
                    const float xv = (&xr[r].x)[u];
                    ull x2;
                    asm("mov.b64 %0, {%1, %1};" : "=l"(x2) : "f"(xv));
                    #pragma unroll
                    for (int c = 0; c < 4; ++c)
                        asm("fma.rn.f32x2 %0, %1, %2, %0;"
                            : "+l"(acc[r][c]) : "l"(x2), "l"(w[c]));
                }
            }
        }

        // Store rows belonging to e_cur (gate-scaled), find next expert in tile.
        int ln = 1 << 30;
        #pragma unroll
        for (int r = 0; r < 4; ++r) {
            const int m = rowbase + r;
            const int em = exp_sm[m];
            if (em > e_cur && em < ln) ln = em;
            if (em != e_cur) continue;
            const float g = gate_sm[m];
            float* dst = g_ybuf + (size_t)ss_sm[m] * DOUT + p;
            #pragma unroll
            for (int c = 0; c < 4; ++c) {
                const float2 v = *(float2*)&acc[r][c];
                float2 o; o.x = v.x * g; o.y = v.y * g;
                *(float2*)(dst + 32 * c) = o;
            }
        }
        if (ln < (1 << 30)) atomicMin(&s_next, ln);
        __syncthreads();
        if (s_next >= (1 << 30)) break;
        e_cur = s_next;
    }
}

// ---------------------------------------------------------------------------
// Kernel C: out[t] = ybuf[2t] + ybuf[2t+1]   (gates already applied)
// ---------------------------------------------------------------------------
__global__ void k_combine(float* __restrict__ out) {
    const int i = blockIdx.x * 256 + threadIdx.x;   // 0 .. NTOK*32-1
    const int t = i >> 5;
    const int q = (i & 31) * 4;
    const float* a = g_ybuf + (size_t)(2 * t) * DOUT + q;
    const float4 va = *(const float4*)a;
    const float4 vb = *(const float4*)(a + DOUT);
    float4 o;
    o.x = va.x + vb.x; o.y = va.y + vb.y;
    o.z = va.z + vb.z; o.w = va.w + vb.w;
    *(float4*)(out + (size_t)t * DOUT + q) = o;
}

// ---------------------------------------------------------------------------
extern "C" void kernel_launch(void* const* d_in, const int* in_sizes, int n_in,
                              void* d_out, int out_size)
{
    const float* inputs = (const float*)d_in[0];
    const float* weight = (const float*)d_in[1];
    const float* gates  = (const float*)d_in[2];

    // Locate sorted_expert_idxs / sorted_scattered_idxs robustly: they are the
    // first two inputs after gates, skipping any scalar (size-1) "k" entry.
    int idxs[2] = {-1, -1};
    int found = 0;
    for (int i = 3; i < n_in && found < 2; ++i) {
        if (in_sizes[i] == 1) continue;   // scalar k
        idxs[found++] = i;
    }
    const int* sei = (const int*)d_in[idxs[0]];
    const int* ssi = (const int*)d_in[idxs[1]];
    float* out = (float*)d_out;
    (void)out_size; (void)weight;

    // Allow 96 KB dynamic smem for the GEMM kernel (deterministic, capture-safe).
    cudaFuncSetAttribute(k_gemm, cudaFuncAttributeMaxDynamicSharedMemorySize, 96 * 1024);

    // A: transpose weights into g_wt
    {
        dim3 grid(4, 4, NEXP), block(32, 8);
        k_transpose<<<grid, block>>>(weight);
    }
    // B: grouped GEMM over sorted slots
    {
        const int nblk = NSLOT / TILE_M;  // 8192
        k_gemm<<<nblk, 256, 96 * 1024>>>(inputs, gates, sei, ssi);
    }
    // C: combine the two gated slot outputs per token
    {
        const int total = NTOK * 32;      // float4 units
        k_combine<<<total / 256, 256>>>(out);
    }
}

// round 4
// speedup vs baseline: 1.3874x; 1.3874x over previous
#include <cuda_runtime.h>
#include <stdint.h>

#define NTOK   262144
#define NSLOT  524288
#define DIN    128
#define DOUT   128
#define NEXP   8
#define TM     128            // slot rows per tile
#define NT     (NSLOT / TM)   // 4096 tiles
#define GRID   148
#define SA     132            // padded smem stride (floats) -> conflict-free frags

typedef unsigned long long ull;

__device__ float g_ybuf[(size_t)NSLOT * DOUT];   // gate-scaled per-slot outputs

// ---------------------------------------------------------------------------
// helpers
// ---------------------------------------------------------------------------
__device__ __forceinline__ uint32_t smem_u32(const void* p) {
    uint32_t a;
    asm("{ .reg .u64 t; cvta.to.shared.u64 t, %1; cvt.u32.u64 %0, t; }" : "=r"(a) : "l"(p));
    return a;
}
__device__ __forceinline__ uint32_t f2tf32(float v) {
    uint32_t u;
    asm("cvt.rna.tf32.f32 %0, %1;" : "=r"(u) : "f"(v));
    return u;
}
__device__ __forceinline__ void cp16(uint32_t dst, const void* src) {
    asm volatile("cp.async.ca.shared.global [%0], [%1], 16;" :: "r"(dst), "l"(src) : "memory");
}
#define CP_COMMIT() asm volatile("cp.async.commit_group;" ::: "memory")
#define CP_WAIT0()  asm volatile("cp.async.wait_group 0;" ::: "memory")

__device__ __forceinline__ void mma_tf32(float* d, const uint32_t* a, const uint32_t* b) {
    asm volatile("mma.sync.aligned.m16n8k8.row.col.f32.tf32.tf32.f32 "
                 "{%0,%1,%2,%3}, {%4,%5,%6,%7}, {%8,%9}, {%0,%1,%2,%3};"
                 : "+f"(d[0]), "+f"(d[1]), "+f"(d[2]), "+f"(d[3])
                 : "r"(a[0]), "r"(a[1]), "r"(a[2]), "r"(a[3]), "r"(b[0]), "r"(b[1]));
}

// ---------------------------------------------------------------------------
// Persistent grouped-GEMM kernel (tf32 mma.sync), tiles striped over CTAs.
// smem: Araw fp32 [128][128] | As tf32 [128][SA] | Bs tf32 [128][SA]
// ---------------------------------------------------------------------------
__global__ void __launch_bounds__(256, 1)
k_moe(const float* __restrict__ inputs,
      const float* __restrict__ weight,   // [E][DOUT][DIN] == B[n][k] row-major
      const float* __restrict__ gates,    // flat [NSLOT]
      const int*   __restrict__ sei,
      const int*   __restrict__ ssi)
{
    extern __shared__ float smraw[];
    float*    Araw = smraw;                              // 16384 f32
    uint32_t* As   = (uint32_t*)(smraw + 16384);         // 128*SA
    uint32_t* Bs   = As + 128 * SA;                      // 128*SA

    __shared__ int   ss2[2][TM];
    __shared__ float gt2[2][TM];
    __shared__ int   ex2[2][TM];
    __shared__ int   seg_e[NEXP + 1];
    __shared__ int   seg_n;

    const int tid  = threadIdx.x;
    const int lane = tid & 31;
    const int wid  = tid >> 5;
    const int wm   = wid >> 1;        // 0..3  -> rows wm*32
    const int wn   = wid & 1;         // 0..1  -> cols wn*64
    const int lr   = lane >> 2;       // 0..7
    const int lc   = lane & 3;        // 0..3

    // ---- prologue: load metadata + issue A prefetch for first tile ----
    int t0 = blockIdx.x;
    if (tid < TM) {
        const int ss = ssi[t0 * TM + tid];
        ss2[0][tid] = ss;
        gt2[0][tid] = gates[ss];
        ex2[0][tid] = sei[t0 * TM + tid];
    }
    __syncthreads();
    {
        const uint32_t abase = smem_u32(Araw);
        #pragma unroll
        for (int it = 0; it < 16; ++it) {
            const int idx = tid + 256 * it;           // float4 units, 4096 total
            const int m = idx >> 5, q = (idx & 31) * 4;
            cp16(abase + (uint32_t)idx * 16,
                 inputs + (size_t)(ss2[0][m] >> 1) * DIN + q);
        }
    }
    CP_COMMIT();

    int par = 0;
    int B_cur = -1;

    for (int t = t0; t < NT; t += GRID) {
        // ---- A raw ready ----
        CP_WAIT0();
        __syncthreads();

        // ---- cvt Araw -> As (tf32, padded stride) ----
        #pragma unroll
        for (int it = 0; it < 16; ++it) {
            const int idx = tid + 256 * it;           // f4 unit, 4096 total
            const int m = idx >> 5, q = (idx & 31) * 4;
            const float4 v = *(const float4*)(Araw + idx * 4);
            uint32_t* d = As + m * SA + q;
            d[0] = f2tf32(v.x); d[1] = f2tf32(v.y);
            d[2] = f2tf32(v.z); d[3] = f2tf32(v.w);
        }
        __syncthreads();   // Araw free, As ready

        // ---- metadata for next tile + segment list for this tile ----
        const int tn = t + GRID;
        if (tid < TM && tn < NT) {
            const int ss = ssi[tn * TM + tid];
            ss2[par ^ 1][tid] = ss;
            gt2[par ^ 1][tid] = gates[ss];
            ex2[par ^ 1][tid] = sei[tn * TM + tid];
        }
        if (tid == 0) {
            int ns = 0, e = ex2[par][0];
            seg_e[ns++] = e;
            for (int i = 1; i < TM; ++i) {
                const int ei = ex2[par][i];
                if (ei != e) { e = ei; seg_e[ns++] = e; }
            }
            seg_n = ns;
        }
        __syncthreads();

        // ---- prefetch next tile's A into Araw ----
        if (tn < NT) {
            const uint32_t abase = smem_u32(Araw);
            #pragma unroll
            for (int it = 0; it < 16; ++it) {
                const int idx = tid + 256 * it;
                const int m = idx >> 5, q = (idx & 31) * 4;
                cp16(abase + (uint32_t)idx * 16,
                     inputs + (size_t)(ss2[par ^ 1][m] >> 1) * DIN + q);
            }
        }
        CP_COMMIT();

        // ---- expert segments ----
        const int nseg = seg_n;
        for (int s = 0; s < nseg; ++s) {
            const int e = seg_e[s];
            if (e != B_cur) {
                __syncthreads();   // all warps done reading old Bs
                const float* Wb = weight + (size_t)e * DOUT * DIN;
                #pragma unroll
                for (int it = 0; it < 16; ++it) {
                    const int idx = tid + 256 * it;    // 4096 f4 units
                    const int n = idx >> 5, q = (idx & 31) * 4;
                    const float4 v = *(const float4*)(Wb + n * DIN + q);
                    uint32_t* d = Bs + n * SA + q;
                    d[0] = f2tf32(v.x); d[1] = f2tf32(v.y);
                    d[2] = f2tf32(v.z); d[3] = f2tf32(v.w);
                }
                B_cur = e;
                __syncthreads();
            }

            // ---- MMA: warp tile 32(M) x 64(N), K=128 ----
            float acc[2][8][4];
            #pragma unroll
            for (int mt = 0; mt < 2; ++mt)
                #pragma unroll
                for (int nt = 0; nt < 8; ++nt)
                    #pragma unroll
                    for (int j = 0; j < 4; ++j) acc[mt][nt][j] = 0.f;

            const int rbase = wm * 32 + lr;
            const int nbase = wn * 64 + lr;
            #pragma unroll
            for (int ks = 0; ks < 16; ++ks) {
                const int k0 = ks * 8;
                uint32_t a[2][4], b[8][2];
                #pragma unroll
                for (int mt = 0; mt < 2; ++mt) {
                    const uint32_t* ap = As + (rbase + mt * 16) * SA + k0 + lc;
                    a[mt][0] = ap[0];
                    a[mt][1] = ap[8 * SA];
                    a[mt][2] = ap[4];
                    a[mt][3] = ap[8 * SA + 4];
                }
                #pragma unroll
                for (int nt = 0; nt < 8; ++nt) {
                    const uint32_t* bp = Bs + (nbase + nt * 8) * SA + k0 + lc;
                    b[nt][0] = bp[0];
                    b[nt][1] = bp[4];
                }
                #pragma unroll
                for (int mt = 0; mt < 2; ++mt)
                    #pragma unroll
                    for (int nt = 0; nt < 8; ++nt)
                        mma_tf32(acc[mt][nt], a[mt], b[nt]);
            }

            // ---- epilogue: gate-scale + scatter rows of this expert ----
            #pragma unroll
            for (int mt = 0; mt < 2; ++mt) {
                #pragma unroll
                for (int half = 0; half < 2; ++half) {
                    const int m = wm * 32 + mt * 16 + lr + half * 8;
                    if (ex2[par][m] != e) continue;
                    const float g = gt2[par][m];
                    float* dst = g_ybuf + (size_t)ss2[par][m] * DOUT + wn * 64 + 2 * lc;
                    #pragma unroll
                    for (int nt = 0; nt < 8; ++nt) {
                        float2 o;
                        o.x = acc[mt][nt][half * 2 + 0] * g;
                        o.y = acc[mt][nt][half * 2 + 1] * g;
                        *(float2*)(dst + nt * 8) = o;
                    }
                }
            }
        }

        par ^= 1;
        __syncthreads();   // epilogue done before metadata buffers flip usage
    }
}

// ---------------------------------------------------------------------------
// Combine: out[t] = ybuf[2t] + ybuf[2t+1] (gates already applied)
// ---------------------------------------------------------------------------
__global__ void k_combine(float* __restrict__ out) {
    const int i = blockIdx.x * 256 + threadIdx.x;   // 0 .. NTOK*32-1
    const int t = i >> 5;
    const int q = (i & 31) * 4;
    const float* a = g_ybuf + (size_t)(2 * t) * DOUT + q;
    const float4 va = *(const float4*)a;
    const float4 vb = *(const float4*)(a + DOUT);
    float4 o;
    o.x = va.x + vb.x; o.y = va.y + vb.y;
    o.z = va.z + vb.z; o.w = va.w + vb.w;
    *(float4*)(out + (size_t)t * DOUT + q) = o;
}

// ---------------------------------------------------------------------------
extern "C" void kernel_launch(void* const* d_in, const int* in_sizes, int n_in,
                              void* d_out, int out_size)
{
    const float* inputs = (const float*)d_in[0];
    const float* weight = (const float*)d_in[1];
    const float* gates  = (const float*)d_in[2];

    int idxs[2] = {-1, -1};
    int found = 0;
    for (int i = 3; i < n_in && found < 2; ++i) {
        if (in_sizes[i] == 1) continue;   // scalar k
        idxs[found++] = i;
    }
    const int* sei = (const int*)d_in[idxs[0]];
    const int* ssi = (const int*)d_in[idxs[1]];
    float* out = (float*)d_out;
    (void)out_size;

    const int smem = 16384 * 4 + 2 * 128 * SA * 4;   // 200704 B
    cudaFuncSetAttribute(k_moe, cudaFuncAttributeMaxDynamicSharedMemorySize, smem);

    k_moe<<<GRID, 256, smem>>>(inputs, weight, gates, sei, ssi);
    k_combine<<<(NTOK * 32) / 256, 256>>>(out);
}

// round 5
// speedup vs baseline: 1.3900x; 1.0018x over previous
#include <cuda_runtime.h>
#include <stdint.h>

#define NTOK   262144
#define NSLOT  524288
#define DIN    128
#define DOUT   128
#define NEXP   8
#define TM     128            // slot rows per tile
#define NT     (NSLOT / TM)   // 4096 tiles
#define GRID   148
#define NTHR   512
#define SA     132            // padded smem stride (floats) -> conflict-free frags

typedef unsigned long long ull;

__device__ float g_ybuf[(size_t)NSLOT * DOUT];   // gate-scaled per-slot outputs

// ---------------------------------------------------------------------------
// helpers
// ---------------------------------------------------------------------------
__device__ __forceinline__ uint32_t smem_u32(const void* p) {
    uint32_t a;
    asm("{ .reg .u64 t; cvta.to.shared.u64 t, %1; cvt.u32.u64 %0, t; }" : "=r"(a) : "l"(p));
    return a;
}
__device__ __forceinline__ uint32_t f2tf32(float v) {
    uint32_t u;
    asm("cvt.rna.tf32.f32 %0, %1;" : "=r"(u) : "f"(v));
    return u;
}
__device__ __forceinline__ void cp16(uint32_t dst, const void* src) {
    asm volatile("cp.async.ca.shared.global [%0], [%1], 16;" :: "r"(dst), "l"(src) : "memory");
}
#define CP_COMMIT() asm volatile("cp.async.commit_group;" ::: "memory")
#define CP_WAIT0()  asm volatile("cp.async.wait_group 0;" ::: "memory")

__device__ __forceinline__ void mma_tf32(float* d, const uint32_t* a, const uint32_t* b) {
    asm volatile("mma.sync.aligned.m16n8k8.row.col.f32.tf32.tf32.f32 "
                 "{%0,%1,%2,%3}, {%4,%5,%6,%7}, {%8,%9}, {%0,%1,%2,%3};"
                 : "+f"(d[0]), "+f"(d[1]), "+f"(d[2]), "+f"(d[3])
                 : "r"(a[0]), "r"(a[1]), "r"(a[2]), "r"(a[3]), "r"(b[0]), "r"(b[1]));
}

// ---------------------------------------------------------------------------
// Persistent grouped-GEMM kernel (tf32 mma.sync), 512 threads, tiles striped
// over CTAs. smem: Araw fp32 [128][128] | As tf32 [128][SA] | Bs tf32 [128][SA]
// ---------------------------------------------------------------------------
__global__ void __launch_bounds__(NTHR, 1)
k_moe(const float* __restrict__ inputs,
      const float* __restrict__ weight,   // [E][DOUT][DIN] == B[n][k] row-major
      const float* __restrict__ gates,    // flat [NSLOT]
      const int*   __restrict__ sei,
      const int*   __restrict__ ssi)
{
    extern __shared__ float smraw[];
    float*    Araw = smraw;                              // 16384 f32
    uint32_t* As   = (uint32_t*)(smraw + 16384);         // 128*SA
    uint32_t* Bs   = As + 128 * SA;                      // 128*SA

    __shared__ int   ss2[2][TM];
    __shared__ float gt2[2][TM];
    __shared__ int   ex2[2][TM];
    __shared__ int   seg_e[NEXP + 1];
    __shared__ int   seg_n;

    const int tid  = threadIdx.x;
    const int lane = tid & 31;
    const int wid  = tid >> 5;        // 0..15
    const int wm   = wid >> 2;        // 0..3  -> rows wm*32
    const int wn   = wid & 3;         // 0..3  -> cols wn*32
    const int lr   = lane >> 2;       // 0..7
    const int lc   = lane & 3;        // 0..3

    // ---- prologue: load metadata + issue A prefetch for first tile ----
    int t0 = blockIdx.x;
    if (tid < TM) {
        const int ss = ssi[t0 * TM + tid];
        ss2[0][tid] = ss;
        gt2[0][tid] = gates[ss];
        ex2[0][tid] = sei[t0 * TM + tid];
    }
    __syncthreads();
    {
        const uint32_t abase = smem_u32(Araw);
        #pragma unroll
        for (int it = 0; it < 8; ++it) {
            const int idx = tid + NTHR * it;          // float4 units, 4096 total
            const int m = idx >> 5, q = (idx & 31) * 4;
            cp16(abase + (uint32_t)idx * 16,
                 inputs + (size_t)(ss2[0][m] >> 1) * DIN + q);
        }
    }
    CP_COMMIT();

    int par = 0;
    int B_cur = -1;

    for (int t = t0; t < NT; t += GRID) {
        // ---- A raw ready ----
        CP_WAIT0();
        __syncthreads();

        // ---- cvt Araw -> As (tf32, padded stride) ----
        #pragma unroll
        for (int it = 0; it < 8; ++it) {
            const int idx = tid + NTHR * it;          // f4 unit, 4096 total
            const int m = idx >> 5, q = (idx & 31) * 4;
            const float4 v = *(const float4*)(Araw + idx * 4);
            uint32_t* d = As + m * SA + q;
            d[0] = f2tf32(v.x); d[1] = f2tf32(v.y);
            d[2] = f2tf32(v.z); d[3] = f2tf32(v.w);
        }
        __syncthreads();   // Araw free, As ready

        // ---- metadata for next tile + segment list for this tile ----
        const int tn = t + GRID;
        if (tid < TM && tn < NT) {
            const int ss = ssi[tn * TM + tid];
            ss2[par ^ 1][tid] = ss;
            gt2[par ^ 1][tid] = gates[ss];
            ex2[par ^ 1][tid] = sei[tn * TM + tid];
        }
        if (tid == 0) {
            int ns = 0, e = ex2[par][0];
            seg_e[ns++] = e;
            for (int i = 1; i < TM; ++i) {
                const int ei = ex2[par][i];
                if (ei != e) { e = ei; seg_e[ns++] = e; }
            }
            seg_n = ns;
        }
        __syncthreads();

        // ---- prefetch next tile's A into Araw ----
        if (tn < NT) {
            const uint32_t abase = smem_u32(Araw);
            #pragma unroll
            for (int it = 0; it < 8; ++it) {
                const int idx = tid + NTHR * it;
                const int m = idx >> 5, q = (idx & 31) * 4;
                cp16(abase + (uint32_t)idx * 16,
                     inputs + (size_t)(ss2[par ^ 1][m] >> 1) * DIN + q);
            }
        }
        CP_COMMIT();

        // ---- expert segments ----
        const int nseg = seg_n;
        for (int s = 0; s < nseg; ++s) {
            const int e = seg_e[s];
            if (e != B_cur) {
                __syncthreads();   // all warps done reading old Bs
                const float* Wb = weight + (size_t)e * DOUT * DIN;
                #pragma unroll
                for (int it = 0; it < 8; ++it) {
                    const int idx = tid + NTHR * it;   // 4096 f4 units
                    const int n = idx >> 5, q = (idx & 31) * 4;
                    const float4 v = *(const float4*)(Wb + n * DIN + q);
                    uint32_t* d = Bs + n * SA + q;
                    d[0] = f2tf32(v.x); d[1] = f2tf32(v.y);
                    d[2] = f2tf32(v.z); d[3] = f2tf32(v.w);
                }
                B_cur = e;
                __syncthreads();
            }

            // ---- MMA: warp tile 32(M) x 32(N), K=128 ----
            float acc[2][4][4];
            #pragma unroll
            for (int mt = 0; mt < 2; ++mt)
                #pragma unroll
                for (int nt = 0; nt < 4; ++nt)
                    #pragma unroll
                    for (int j = 0; j < 4; ++j) acc[mt][nt][j] = 0.f;

            const int rbase = wm * 32 + lr;
            const int nbase = wn * 32 + lr;
            #pragma unroll
            for (int ks = 0; ks < 16; ++ks) {
                const int k0 = ks * 8;
                uint32_t a[2][4], b[4][2];
                #pragma unroll
                for (int mt = 0; mt < 2; ++mt) {
                    const uint32_t* ap = As + (rbase + mt * 16) * SA + k0 + lc;
                    a[mt][0] = ap[0];
                    a[mt][1] = ap[8 * SA];
                    a[mt][2] = ap[4];
                    a[mt][3] = ap[8 * SA + 4];
                }
                #pragma unroll
                for (int nt = 0; nt < 4; ++nt) {
                    const uint32_t* bp = Bs + (nbase + nt * 8) * SA + k0 + lc;
                    b[nt][0] = bp[0];
                    b[nt][1] = bp[4];
                }
                #pragma unroll
                for (int mt = 0; mt < 2; ++mt)
                    #pragma unroll
                    for (int nt = 0; nt < 4; ++nt)
                        mma_tf32(acc[mt][nt], a[mt], b[nt]);
            }

            // ---- epilogue: gate-scale + scatter rows of this expert ----
            #pragma unroll
            for (int mt = 0; mt < 2; ++mt) {
                #pragma unroll
                for (int half = 0; half < 2; ++half) {
                    const int m = wm * 32 + mt * 16 + lr + half * 8;
                    if (ex2[par][m] != e) continue;
                    const float g = gt2[par][m];
                    float* dst = g_ybuf + (size_t)ss2[par][m] * DOUT + wn * 32 + 2 * lc;
                    #pragma unroll
                    for (int nt = 0; nt < 4; ++nt) {
                        float2 o;
                        o.x = acc[mt][nt][half * 2 + 0] * g;
                        o.y = acc[mt][nt][half * 2 + 1] * g;
                        *(float2*)(dst + nt * 8) = o;
                    }
                }
            }
        }

        par ^= 1;
        __syncthreads();   // epilogue done before metadata buffers flip usage
    }
}

// ---------------------------------------------------------------------------
// Combine: out[t] = ybuf[2t] + ybuf[2t+1] (gates already applied)
// ---------------------------------------------------------------------------
__global__ void k_combine(float* __restrict__ out) {
    const int i = blockIdx.x * 256 + threadIdx.x;   // 0 .. NTOK*32-1
    const int t = i >> 5;
    const int q = (i & 31) * 4;
    const float* a = g_ybuf + (size_t)(2 * t) * DOUT + q;
    const float4 va = *(const float4*)a;
    const float4 vb = *(const float4*)(a + DOUT);
    float4 o;
    o.x = va.x + vb.x; o.y = va.y + vb.y;
    o.z = va.z + vb.z; o.w = va.w + vb.w;
    *(float4*)(out + (size_t)t * DOUT + q) = o;
}

// ---------------------------------------------------------------------------
extern "C" void kernel_launch(void* const* d_in, const int* in_sizes, int n_in,
                              void* d_out, int out_size)
{
    const float* inputs = (const float*)d_in[0];
    const float* weight = (const float*)d_in[1];
    const float* gates  = (const float*)d_in[2];

    int idxs[2] = {-1, -1};
    int found = 0;
    for (int i = 3; i < n_in && found < 2; ++i) {
        if (in_sizes[i] == 1) continue;   // scalar k
        idxs[found++] = i;
    }
    const int* sei = (const int*)d_in[idxs[0]];
    const int* ssi = (const int*)d_in[idxs[1]];
    float* out = (float*)d_out;
    (void)out_size;

    const int smem = 16384 * 4 + 2 * 128 * SA * 4;   // 200704 B
    cudaFuncSetAttribute(k_moe, cudaFuncAttributeMaxDynamicSharedMemorySize, smem);

    k_moe<<<GRID, NTHR, smem>>>(inputs, weight, gates, sei, ssi);
    k_combine<<<(NTOK * 32) / 256, 256>>>(out);
}

// round 6
// speedup vs baseline: 1.6404x; 1.1802x over previous
#include <cuda_runtime.h>
#include <cuda_fp16.h>
#include <stdint.h>

#define NTOK   262144
#define NSLOT  524288
#define DIN    128
#define DOUT   128
#define NEXP   8
#define TM     128            // slot rows per tile
#define NT     (NSLOT / TM)   // 4096 tiles
#define GRID   148
#define NTHR   512
#define SAR    132            // Araw padded stride (floats)

typedef unsigned long long ull;

__device__ float g_ybuf[(size_t)NSLOT * DOUT];   // gate-scaled per-slot outputs

// ---------------------------------------------------------------------------
// helpers
// ---------------------------------------------------------------------------
__device__ __forceinline__ uint32_t smem_u32(const void* p) {
    uint32_t a;
    asm("{ .reg .u64 t; cvta.to.shared.u64 t, %1; cvt.u32.u64 %0, t; }" : "=r"(a) : "l"(p));
    return a;
}
// pack two fp32 -> fp16x2 (lo = x, hi = y)
__device__ __forceinline__ uint32_t pack_h2(float x, float y) {
    uint32_t u;
    asm("cvt.rn.f16x2.f32 %0, %1, %2;" : "=r"(u) : "f"(y), "f"(x));
    return u;
}
__device__ __forceinline__ void cp16(uint32_t dst, const void* src) {
    asm volatile("cp.async.ca.shared.global [%0], [%1], 16;" :: "r"(dst), "l"(src) : "memory");
}
#define CP_COMMIT() asm volatile("cp.async.commit_group;" ::: "memory")
#define CP_WAIT0()  asm volatile("cp.async.wait_group 0;" ::: "memory")

// m16n8k16 fp16 -> fp32 acc
__device__ __forceinline__ void mma_f16(float* d, const uint32_t* a, uint32_t b0, uint32_t b1) {
    asm volatile("mma.sync.aligned.m16n8k16.row.col.f32.f16.f16.f32 "
                 "{%0,%1,%2,%3}, {%4,%5,%6,%7}, {%8,%9}, {%0,%1,%2,%3};"
                 : "+f"(d[0]), "+f"(d[1]), "+f"(d[2]), "+f"(d[3])
                 : "r"(a[0]), "r"(a[1]), "r"(a[2]), "r"(a[3]), "r"(b0), "r"(b1));
}

// ---------------------------------------------------------------------------
// Persistent grouped-GEMM (fp16 mma.sync, fragment-major smem), 512 threads.
// smem: Araw fp32 [128][SAR] | As_frag uint4[8*8*32] | B_frag uint4[8*8*32]
//   As_frag[R(16-row blk)][ks][lane] = {a0,a1,a2,a3}
//   B_frag [np(16-n blk)][ks][lane]  = {b0,b1 of n8 blk 2np, b0,b1 of 2np+1}
// ---------------------------------------------------------------------------
__global__ void __launch_bounds__(NTHR, 1)
k_moe(const float* __restrict__ inputs,
      const float* __restrict__ weight,   // [E][DOUT][DIN] == W[n][k] row-major
      const float* __restrict__ gates,    // flat [NSLOT]
      const int*   __restrict__ sei,
      const int*   __restrict__ ssi)
{
    extern __shared__ float smraw[];
    float* Araw   = smraw;                                   // 128*SAR f32
    uint4* As_frag = (uint4*)(smraw + 128 * SAR);            // 2048 uint4
    uint4* B_frag  = As_frag + 8 * 8 * 32;                   // 2048 uint4

    __shared__ int   ss2[2][TM];
    __shared__ float gt2[2][TM];
    __shared__ int   ex2[2][TM];
    __shared__ int   seg_e[NEXP + 1];
    __shared__ int   seg_n;

    const int tid  = threadIdx.x;
    const int lane = tid & 31;
    const int wid  = tid >> 5;        // 0..15
    const int wm   = wid >> 2;        // 0..3  -> rows wm*32
    const int wn   = wid & 3;         // 0..3  -> cols wn*32
    const int gr   = lane >> 2;       // 0..7
    const int tc   = lane & 3;        // 0..3

    // ---- prologue: metadata + first A prefetch ----
    int t0 = blockIdx.x;
    if (tid < TM) {
        const int ss = ssi[t0 * TM + tid];
        ss2[0][tid] = ss;
        gt2[0][tid] = gates[ss];
        ex2[0][tid] = sei[t0 * TM + tid];
    }
    __syncthreads();
    {
        const uint32_t abase = smem_u32(Araw);
        #pragma unroll
        for (int it = 0; it < 8; ++it) {
            const int idx = tid + NTHR * it;          // 4096 float4 units
            const int m = idx >> 5, q = (idx & 31) * 4;
            cp16(abase + (uint32_t)(m * SAR + q) * 4,
                 inputs + (size_t)(ss2[0][m] >> 1) * DIN + q);
        }
    }
    CP_COMMIT();

    int par = 0;
    int B_cur = -1;

    for (int t = t0; t < NT; t += GRID) {
        CP_WAIT0();
        __syncthreads();   // Araw ready; prior-tile MMA done with As_frag

        // ---- cvt Araw(fp32) -> As_frag(fp16 fragments) ----
        // warp w: R = w>>1, ks in 4*(w&1) .. +3
        {
            const int R = wid >> 1;
            const int ks0 = (wid & 1) * 4;
            const int row = R * 16 + gr;
            #pragma unroll
            for (int i = 0; i < 4; ++i) {
                const int ks = ks0 + i;
                const int c0 = ks * 16 + tc * 2;
                const float2 v00 = *(const float2*)(Araw + row * SAR + c0);
                const float2 v10 = *(const float2*)(Araw + (row + 8) * SAR + c0);
                const float2 v01 = *(const float2*)(Araw + row * SAR + c0 + 8);
                const float2 v11 = *(const float2*)(Araw + (row + 8) * SAR + c0 + 8);
                uint4 f;
                f.x = pack_h2(v00.x, v00.y);
                f.y = pack_h2(v10.x, v10.y);
                f.z = pack_h2(v01.x, v01.y);
                f.w = pack_h2(v11.x, v11.y);
                As_frag[(R * 8 + ks) * 32 + lane] = f;
            }
        }
        __syncthreads();   // Araw free, As_frag ready

        // ---- next-tile metadata + segment list ----
        const int tn = t + GRID;
        if (tid < TM && tn < NT) {
            const int ss = ssi[tn * TM + tid];
            ss2[par ^ 1][tid] = ss;
            gt2[par ^ 1][tid] = gates[ss];
            ex2[par ^ 1][tid] = sei[tn * TM + tid];
        }
        if (tid == 0) {
            int ns = 0, e = ex2[par][0];
            seg_e[ns++] = e;
            for (int i = 1; i < TM; ++i) {
                const int ei = ex2[par][i];
                if (ei != e) { e = ei; seg_e[ns++] = e; }
            }
            seg_n = ns;
        }
        __syncthreads();

        // ---- prefetch next tile's A into Araw ----
        if (tn < NT) {
            const uint32_t abase = smem_u32(Araw);
            #pragma unroll
            for (int it = 0; it < 8; ++it) {
                const int idx = tid + NTHR * it;
                const int m = idx >> 5, q = (idx & 31) * 4;
                cp16(abase + (uint32_t)(m * SAR + q) * 4,
                     inputs + (size_t)(ss2[par ^ 1][m] >> 1) * DIN + q);
            }
        }
        CP_COMMIT();

        // ---- expert segments ----
        const int nseg = seg_n;
        for (int s = 0; s < nseg; ++s) {
            const int e = seg_e[s];
            if (e != B_cur) {
                __syncthreads();   // all warps done reading old B_frag
                // warp w converts n8 block b = w
                const int b = wid;
                const float* Wrow = weight + (size_t)e * DOUT * DIN + (b * 8 + gr) * DIN;
                uint2* dst2 = (uint2*)B_frag;   // 2 uint2 per uint4
                #pragma unroll
                for (int ks = 0; ks < 8; ++ks) {
                    const int k0 = ks * 16 + tc * 2;
                    const float2 w0 = *(const float2*)(Wrow + k0);
                    const float2 w1 = *(const float2*)(Wrow + k0 + 8);
                    uint2 f;
                    f.x = pack_h2(w0.x, w0.y);
                    f.y = pack_h2(w1.x, w1.y);
                    dst2[(((b >> 1) * 8 + ks) * 32 + lane) * 2 + (b & 1)] = f;
                }
                B_cur = e;
                __syncthreads();
            }

            // ---- MMA: warp tile 32(M) x 32(N), K=128, 8 ks slices ----
            float acc[2][4][4];
            #pragma unroll
            for (int mt = 0; mt < 2; ++mt)
                #pragma unroll
                for (int nt = 0; nt < 4; ++nt)
                    #pragma unroll
                    for (int j = 0; j < 4; ++j) acc[mt][nt][j] = 0.f;

            const int R0  = wm * 2;
            const int np0 = wn * 2;
            #pragma unroll
            for (int ks = 0; ks < 8; ++ks) {
                const uint4 A0 = As_frag[(R0 * 8 + ks) * 32 + lane];
                const uint4 A1 = As_frag[((R0 + 1) * 8 + ks) * 32 + lane];
                const uint4 B0 = B_frag[(np0 * 8 + ks) * 32 + lane];
                const uint4 B1 = B_frag[((np0 + 1) * 8 + ks) * 32 + lane];
                const uint32_t a0[4] = {A0.x, A0.y, A0.z, A0.w};
                const uint32_t a1[4] = {A1.x, A1.y, A1.z, A1.w};
                mma_f16(acc[0][0], a0, B0.x, B0.y);
                mma_f16(acc[0][1], a0, B0.z, B0.w);
                mma_f16(acc[0][2], a0, B1.x, B1.y);
                mma_f16(acc[0][3], a0, B1.z, B1.w);
                mma_f16(acc[1][0], a1, B0.x, B0.y);
                mma_f16(acc[1][1], a1, B0.z, B0.w);
                mma_f16(acc[1][2], a1, B1.x, B1.y);
                mma_f16(acc[1][3], a1, B1.z, B1.w);
            }

            // ---- epilogue: gate-scale + scatter rows of this expert ----
            #pragma unroll
            for (int mt = 0; mt < 2; ++mt) {
                #pragma unroll
                for (int half = 0; half < 2; ++half) {
                    const int m = wm * 32 + mt * 16 + gr + half * 8;
                    if (ex2[par][m] != e) continue;
                    const float g = gt2[par][m];
                    float* dst = g_ybuf + (size_t)ss2[par][m] * DOUT + wn * 32 + 2 * tc;
                    #pragma unroll
                    for (int nt = 0; nt < 4; ++nt) {
                        float2 o;
                        o.x = acc[mt][nt][half * 2 + 0] * g;
                        o.y = acc[mt][nt][half * 2 + 1] * g;
                        *(float2*)(dst + nt * 8) = o;
                    }
                }
            }
        }

        par ^= 1;
        __syncthreads();   // epilogue done before buffers flip
    }
}

// ---------------------------------------------------------------------------
// Combine: out[t] = ybuf[2t] + ybuf[2t+1] (gates already applied)
// ---------------------------------------------------------------------------
__global__ void k_combine(float* __restrict__ out) {
    const int i = blockIdx.x * 256 + threadIdx.x;   // 0 .. NTOK*32-1
    const int t = i >> 5;
    const int q = (i & 31) * 4;
    const float* a = g_ybuf + (size_t)(2 * t) * DOUT + q;
    const float4 va = *(const float4*)a;
    const float4 vb = *(const float4*)(a + DOUT);
    float4 o;
    o.x = va.x + vb.x; o.y = va.y + vb.y;
    o.z = va.z + vb.z; o.w = va.w + vb.w;
    *(float4*)(out + (size_t)t * DOUT + q) = o;
}

// ---------------------------------------------------------------------------
extern "C" void kernel_launch(void* const* d_in, const int* in_sizes, int n_in,
                              void* d_out, int out_size)
{
    const float* inputs = (const float*)d_in[0];
    const float* weight = (const float*)d_in[1];
    const float* gates  = (const float*)d_in[2];

    int idxs[2] = {-1, -1};
    int found = 0;
    for (int i = 3; i < n_in && found < 2; ++i) {
        if (in_sizes[i] == 1) continue;   // scalar k
        idxs[found++] = i;
    }
    const int* sei = (const int*)d_in[idxs[0]];
    const int* ssi = (const int*)d_in[idxs[1]];
    float* out = (float*)d_out;
    (void)out_size;

    const int smem = 128 * SAR * 4 + 2 * 2048 * 16;   // 67584 + 65536 = 133120
    cudaFuncSetAttribute(k_moe, cudaFuncAttributeMaxDynamicSharedMemorySize, smem);

    k_moe<<<GRID, NTHR, smem>>>(inputs, weight, gates, sei, ssi);
    k_combine<<<(NTOK * 32) / 256, 256>>>(out);
}